// round 4
// baseline (speedup 1.0000x reference)
#include <cuda_runtime.h>
#include <cstdint>

// ---------------- problem constants (fixed by the reference) ----------------
#define EMBD   256
#define HIDDEN 256
#define HNUM   8
#define CHD    32
#define BATCH  8
#define NQ     1024
#define ITOT   21760           // 128^2 + 64^2 + 32^2 + 16^2
#define QPW    384             // H*L*P*3
#define GK     256             // K for every GEMM

// ---------------- scratch (no allocations allowed) ----------------
__device__ float  g_img_p[BATCH * ITOT * HIDDEN];     // projected pyramid  (~178 MB)
__device__ float  g_Wt1[HIDDEN * GK];                 // W_img^T  [N,K], tf32-rounded
__device__ float  g_Wt2[QPW * GK];                    // W_q^T    [N,K]
__device__ float  g_Wt3[EMBD * GK];                   // W_out^T  [N,K]
__device__ float  g_qp[BATCH * NQ * QPW];             // query projection
__device__ float  g_attn[BATCH * NQ * HNUM * 16];     // softmaxed attention
__device__ float2 g_coords[BATCH * NQ * HNUM * 16];   // sampling points (normalized)
__device__ float  g_hidden[BATCH * NQ * HIDDEN];      // sampled context

__constant__ int c_sh[4]    = {128, 64, 32, 16};
__constant__ int c_start[4] = {0, 16384, 20480, 21504};

// ---------------- helpers ----------------
__device__ __forceinline__ void cp16(uint32_t dst, const void* src) {
    asm volatile("cp.async.cg.shared.global [%0], [%1], 16;" :: "r"(dst), "l"(src));
}
__device__ __forceinline__ uint32_t smem_u32(const void* p) {
    uint32_t a;
    asm("{ .reg .u64 t; cvta.to.shared.u64 t, %1; cvt.u32.u64 %0, t; }" : "=r"(a) : "l"(p));
    return a;
}
__device__ __forceinline__ uint32_t f2tf32(float f) {
    uint32_t r;
    asm("cvt.rna.tf32.f32 %0, %1;" : "=r"(r) : "f"(f));
    return r;
}

// =============== mma.sync tf32 GEMM: C[M,N] = A[M,256] @ Wt[N,256]^T + bias ===============
// CTA tile 128x64, 8 warps in 4(M)x2(N), warp tile 32x32, k-step 16,
// 3-stage cp.async pipeline.  Wt is [N,K] row-major, tf32-rounded.
// Requires M%128==0, N%64==0.  A tiles shared across concurrent n-CTAs via L2.

#define ROWPAD  20             // 16 floats + 4 pad (conflict-free fragment loads)
#define STG_ROWS 192           // 128 A rows + 64 B rows
#define STG_FLTS (STG_ROWS * ROWPAD)
#define NSTAGE  3
#define NKT     (GK / 16)      // 16 k-tiles

__global__ __launch_bounds__(256, 3) void mma_gemm(
    const float* __restrict__ A, const float* __restrict__ Wt,
    const float* __restrict__ bias, float* __restrict__ C,
    int M, int N)
{
    __shared__ float sm[NSTAGE][STG_FLTS];   // 3 * 15360 B = 45 KB

    const int tid = threadIdx.x;
    const int wid = tid >> 5;
    const int lane = tid & 31;
    const int g = lane >> 2;           // groupID 0..7
    const int tig = lane & 3;          // thread-in-group
    const int m0 = blockIdx.y * 128;
    const int n0 = blockIdx.x * 64;
    const int wm = (wid & 3) * 32;     // warp M offset (4 warps)
    const int wn = (wid >> 2) * 32;    // warp N offset (2 warps)

    float acc[2][4][4];
    #pragma unroll
    for (int i = 0; i < 2; i++)
        #pragma unroll
        for (int j = 0; j < 4; j++)
            #pragma unroll
            for (int r = 0; r < 4; r++) acc[i][j][r] = 0.f;

    uint32_t smb[NSTAGE];
    #pragma unroll
    for (int s = 0; s < NSTAGE; s++) smb[s] = smem_u32(&sm[s][0]);

    // stage loader: 768 16B-chunks (A: 512, B: 256), 3 per thread
    auto load_stage = [&](uint32_t sb, int kt) {
        #pragma unroll
        for (int i = 0; i < 3; i++) {
            int id = i * 256 + tid;
            int half = id >> 9;                 // 0 = A (512 chunks), 1 = B (256)
            int rid = half ? (id - 512) : id;
            int row = rid >> 2;
            int c = rid & 3;
            const float* src = half
                ? Wt + (size_t)(n0 + row) * GK + kt * 16 + c * 4
                : A  + (size_t)(m0 + row) * GK + kt * 16 + c * 4;
            cp16(sb + (uint32_t)((half * 128 + row) * ROWPAD + c * 4) * 4, src);
        }
    };

    load_stage(smb[0], 0);
    asm volatile("cp.async.commit_group;" ::: "memory");
    load_stage(smb[1], 1);
    asm volatile("cp.async.commit_group;" ::: "memory");

    #pragma unroll 1
    for (int kt = 0; kt < NKT; kt++) {
        if (kt < NKT - 1) {
            asm volatile("cp.async.wait_group 1;" ::: "memory");
        } else {
            asm volatile("cp.async.wait_group 0;" ::: "memory");
        }
        __syncthreads();

        if (kt + 2 < NKT) {
            load_stage(smb[(kt + 2) % NSTAGE], kt + 2);
            asm volatile("cp.async.commit_group;" ::: "memory");
        }

        const float* As = sm[kt % NSTAGE];
        const float* Bs = sm[kt % NSTAGE] + 128 * ROWPAD;

        #pragma unroll
        for (int ks = 0; ks < 2; ks++) {
            const int kb = ks * 8;
            uint32_t a[2][4], b[4][2];
            #pragma unroll
            for (int mf = 0; mf < 2; mf++) {
                int r = wm + mf * 16 + g;
                a[mf][0] = f2tf32(As[r * ROWPAD + kb + tig]);
                a[mf][1] = f2tf32(As[(r + 8) * ROWPAD + kb + tig]);
                a[mf][2] = f2tf32(As[r * ROWPAD + kb + tig + 4]);
                a[mf][3] = f2tf32(As[(r + 8) * ROWPAD + kb + tig + 4]);
            }
            #pragma unroll
            for (int nf = 0; nf < 4; nf++) {
                int r = wn + nf * 8 + g;
                b[nf][0] = __float_as_uint(Bs[r * ROWPAD + kb + tig]);     // pre-rounded
                b[nf][1] = __float_as_uint(Bs[r * ROWPAD + kb + tig + 4]);
            }
            #pragma unroll
            for (int mf = 0; mf < 2; mf++)
                #pragma unroll
                for (int nf = 0; nf < 4; nf++) {
                    asm volatile(
                        "mma.sync.aligned.m16n8k8.row.col.f32.tf32.tf32.f32 "
                        "{%0,%1,%2,%3}, {%4,%5,%6,%7}, {%8,%9}, {%0,%1,%2,%3};"
                        : "+f"(acc[mf][nf][0]), "+f"(acc[mf][nf][1]),
                          "+f"(acc[mf][nf][2]), "+f"(acc[mf][nf][3])
                        : "r"(a[mf][0]), "r"(a[mf][1]), "r"(a[mf][2]), "r"(a[mf][3]),
                          "r"(b[nf][0]), "r"(b[nf][1]));
                }
        }
    }

    // epilogue: add bias, write float2 pairs
    #pragma unroll
    for (int nf = 0; nf < 4; nf++) {
        const int col = n0 + wn + nf * 8 + tig * 2;
        const float2 bb = *(const float2*)(bias + col);
        #pragma unroll
        for (int mf = 0; mf < 2; mf++) {
            const int row = m0 + wm + mf * 16 + g;
            float2 v0 = make_float2(acc[mf][nf][0] + bb.x, acc[mf][nf][1] + bb.y);
            float2 v1 = make_float2(acc[mf][nf][2] + bb.x, acc[mf][nf][3] + bb.y);
            *(float2*)(C + (size_t)row * N + col) = v0;
            *(float2*)(C + (size_t)(row + 8) * N + col) = v1;
        }
    }
}

// W [K=256, N] row-major  ->  Wt [N, K] row-major, tf32-rounded
__global__ void pack_wt(const float* __restrict__ W, float* __restrict__ Wt, int N) {
    __shared__ float t[32][33];
    int bx = blockIdx.x * 32;   // n tile
    int by = blockIdx.y * 32;   // k tile
    int x = threadIdx.x, y = threadIdx.y;
    #pragma unroll
    for (int i = 0; i < 32; i += 8)
        t[y + i][x] = W[(size_t)(by + y + i) * N + bx + x];
    __syncthreads();
    #pragma unroll
    for (int i = 0; i < 32; i += 8) {
        float v = t[x][y + i];
        Wt[(size_t)(bx + y + i) * GK + by + x] = __uint_as_float(f2tf32(v));
    }
}

// ---------------- softmax + sampling-coordinate precompute ----------------
__global__ void softmax_coords(const float* __restrict__ qp,
                               const float* __restrict__ refpts,
                               float* __restrict__ attn,
                               float2* __restrict__ coords)
{
    int t = blockIdx.x * blockDim.x + threadIdx.x;
    if (t >= BATCH * NQ * HNUM) return;
    int bn = t / HNUM;

    const float* q = qp + (size_t)t * 48;

    float lg[16];
    float mx = -1e30f;
    #pragma unroll
    for (int s = 0; s < 16; s++) { lg[s] = q[s * 3 + 2]; mx = fmaxf(mx, lg[s]); }
    float sum = 0.f;
    #pragma unroll
    for (int s = 0; s < 16; s++) { lg[s] = expf(lg[s] - mx); sum += lg[s]; }
    float inv = 1.0f / sum;

    float rx = refpts[bn * 2 + 0];
    float ry = refpts[bn * 2 + 1];

    #pragma unroll
    for (int s = 0; s < 16; s++) {
        int l = s >> 2;
        float sh = (float)c_sh[l];
        attn[(size_t)t * 16 + s] = lg[s] * inv;
        float ox = q[s * 3 + 0];
        float oy = q[s * 3 + 1];
        coords[(size_t)t * 16 + s] = make_float2(rx + ox / sh, ry + oy / sh);
    }
}

// ---------------- bilinear sampling + attention reduce ----------------
__global__ __launch_bounds__(256) void msda_sample(
    const float* __restrict__ img_p,
    const float* __restrict__ attn,
    const float2* __restrict__ coords,
    float* __restrict__ out)
{
    int w = blockIdx.x * 8 + (threadIdx.x >> 5);
    int lane = threadIdx.x & 31;

    int h = w % HNUM;
    int b = w / (NQ * HNUM);

    const size_t img_base = (size_t)b * ITOT * HIDDEN + h * CHD + lane;
    const float*  ap = attn   + (size_t)w * 16;
    const float2* cp = coords + (size_t)w * 16;

    float acc = 0.f;

    #pragma unroll
    for (int s = 0; s < 16; s++) {
        int l = s >> 2;
        int sh = c_sh[l];
        float fs = (float)sh;
        int st = c_start[l];

        float aw = ap[s];
        float2 c = cp[s];

        float x = c.x * fs - 0.5f;
        float y = c.y * fs - 0.5f;
        float x0f = floorf(x), y0f = floorf(y);
        int x0 = (int)x0f, y0 = (int)y0f;
        float wx = x - x0f, wy = y - y0f;

        float w00 = (1.f - wx) * (1.f - wy) * aw;
        float w10 = wx * (1.f - wy) * aw;
        float w01 = (1.f - wx) * wy * aw;
        float w11 = wx * wy * aw;

        bool vx0 = (x0 >= 0) & (x0 < sh);
        bool vx1 = (x0 + 1 >= 0) & (x0 + 1 < sh);
        bool vy0 = (y0 >= 0) & (y0 < sh);
        bool vy1 = (y0 + 1 >= 0) & (y0 + 1 < sh);

        if (vx0 & vy0) acc += w00 * img_p[img_base + (size_t)(st + y0 * sh + x0) * HIDDEN];
        if (vx1 & vy0) acc += w10 * img_p[img_base + (size_t)(st + y0 * sh + x0 + 1) * HIDDEN];
        if (vx0 & vy1) acc += w01 * img_p[img_base + (size_t)(st + (y0 + 1) * sh + x0) * HIDDEN];
        if (vx1 & vy1) acc += w11 * img_p[img_base + (size_t)(st + (y0 + 1) * sh + x0 + 1) * HIDDEN];
    }

    out[(size_t)w * CHD + lane] = acc;
}

// ---------------- launch ----------------
extern "C" void kernel_launch(void* const* d_in, const int* in_sizes, int n_in,
                              void* d_out, int out_size)
{
    const float* img     = (const float*)d_in[0];
    const float* queries = (const float*)d_in[2];
    const float* refpts  = (const float*)d_in[3];
    const float* W_img   = (const float*)d_in[4];
    const float* b_img   = (const float*)d_in[5];
    const float* W_q     = (const float*)d_in[6];
    const float* b_q     = (const float*)d_in[7];
    const float* W_out   = (const float*)d_in[8];
    const float* b_out   = (const float*)d_in[9];
    float* out = (float*)d_out;

    float *img_p, *qp, *attn, *hidden, *Wt1, *Wt2, *Wt3;
    float2* coords;
    cudaGetSymbolAddress((void**)&img_p,  g_img_p);
    cudaGetSymbolAddress((void**)&qp,     g_qp);
    cudaGetSymbolAddress((void**)&attn,   g_attn);
    cudaGetSymbolAddress((void**)&coords, g_coords);
    cudaGetSymbolAddress((void**)&hidden, g_hidden);
    cudaGetSymbolAddress((void**)&Wt1,    g_Wt1);
    cudaGetSymbolAddress((void**)&Wt2,    g_Wt2);
    cudaGetSymbolAddress((void**)&Wt3,    g_Wt3);

    // 0) pack weights: transpose to [N,K] + tf32 rounding
    {
        dim3 blk(32, 8);
        pack_wt<<<dim3(HIDDEN / 32, GK / 32), blk>>>(W_img, Wt1, HIDDEN);
        pack_wt<<<dim3(QPW    / 32, GK / 32), blk>>>(W_q,   Wt2, QPW);
        pack_wt<<<dim3(EMBD   / 32, GK / 32), blk>>>(W_out, Wt3, EMBD);
    }
    // 1) img projection: [174080,256] @ [256,256] + b
    mma_gemm<<<dim3(HIDDEN / 64, (BATCH * ITOT) / 128), 256>>>(
        img, Wt1, b_img, img_p, BATCH * ITOT, HIDDEN);
    // 2) query projection: [8192,256] @ [256,384] + b
    mma_gemm<<<dim3(QPW / 64, (BATCH * NQ) / 128), 256>>>(
        queries, Wt2, b_q, qp, BATCH * NQ, QPW);
    // 3) softmax + sampling coords
    {
        int total = BATCH * NQ * HNUM;
        softmax_coords<<<(total + 255) / 256, 256>>>(qp, refpts, attn, coords);
    }
    // 4) bilinear sampling + attention reduce
    msda_sample<<<(BATCH * NQ * HNUM) / 8, 256>>>(img_p, attn, coords, hidden);
    // 5) output projection: [8192,256] @ [256,256] + b
    mma_gemm<<<dim3(HIDDEN / 64, (BATCH * NQ) / 128), 256>>>(
        hidden, Wt3, b_out, out, BATCH * NQ, HIDDEN);
}

// round 5
// speedup vs baseline: 1.1794x; 1.1794x over previous
#include <cuda_runtime.h>
#include <cuda_fp16.h>
#include <cstdint>

// ---------------- problem constants (fixed by the reference) ----------------
#define EMBD   256
#define HIDDEN 256
#define HNUM   8
#define CHD    32
#define BATCH  8
#define NQ     1024
#define ITOT   21760           // 128^2 + 64^2 + 32^2 + 16^2
#define QPW    384             // H*L*P*3
#define GK     256             // K for every GEMM
#define BNH    (BATCH * NQ * HNUM)   // 65536

// ---------------- scratch (no allocations allowed) ----------------
__device__ float   g_img_p[BATCH * ITOT * HIDDEN];   // projected pyramid (~178 MB)
__device__ __half  g_Wt1[HIDDEN * GK];               // W_img^T [N,K] fp16
__device__ __half  g_Wt2[QPW * GK];                  // W_q^T   [N,K] fp16
__device__ __half  g_Wt3[EMBD * GK];                 // W_out^T [N,K] fp16
__device__ float   g_qp[BATCH * NQ * QPW];           // query projection
__device__ float4  g_sw[BNH * 16];                   // 4 corner weights (x attn)
__device__ int4    g_si[BNH * 16];                   // 4 corner indices (x HIDDEN)
__device__ float   g_hidden[BATCH * NQ * HIDDEN];    // sampled context

__constant__ int c_sh[4]    = {128, 64, 32, 16};
__constant__ int c_start[4] = {0, 16384, 20480, 21504};

// ---------------- helpers ----------------
__device__ __forceinline__ void cp16(uint32_t dst, const void* src) {
    asm volatile("cp.async.cg.shared.global [%0], [%1], 16;" :: "r"(dst), "l"(src));
}
__device__ __forceinline__ uint32_t smem_u32(const void* p) {
    uint32_t a;
    asm("{ .reg .u64 t; cvta.to.shared.u64 t, %1; cvt.u32.u64 %0, t; }" : "=r"(a) : "l"(p));
    return a;
}
__device__ __forceinline__ uint32_t pack_h2(float2 v) {  // lo = v.x, hi = v.y
    uint32_t r;
    asm("cvt.rn.f16x2.f32 %0, %1, %2;" : "=r"(r) : "f"(v.y), "f"(v.x));
    return r;
}

// =============== fp16 mma.sync GEMM: C[M,N] = A[M,256] @ Wt[N,256]^T + bias ===============
// CTA tile 128x64, 8 warps 4(M)x2(N), warp tile 32x32, k-step 16 (one m16n8k16 per frag),
// 3-stage cp.async.  A fp32 in smem (converted in-register), Wt fp16 [N,K].
// Requires M%128==0, N%64==0.

#define ROWPAD  20                   // A: 16 floats + 4 pad  (perfect 2-way for LDS.64)
#define BPITCH  24                   // B: 16 halves + 8 pad  (conflict-free .b32)
#define A_STG   (128 * ROWPAD)       // floats per stage
#define B_STG   (64 * BPITCH)        // halves per stage
#define NSTAGE  3
#define NKT     (GK / 16)            // 16 k-tiles

__global__ __launch_bounds__(256) void hgemm(
    const float* __restrict__ A, const __half* __restrict__ Wt,
    const float* __restrict__ bias, float* __restrict__ C,
    int M, int N)
{
    __shared__ float  sA[NSTAGE][A_STG];   // 3 * 10240 B
    __shared__ __half sB[NSTAGE][B_STG];   // 3 *  3072 B

    const int tid = threadIdx.x;
    const int wid = tid >> 5;
    const int lane = tid & 31;
    const int g = lane >> 2;           // groupID 0..7
    const int tig = lane & 3;          // thread-in-group
    const int m0 = blockIdx.y * 128;
    const int n0 = blockIdx.x * 64;
    const int wm = (wid & 3) * 32;     // warp M offset
    const int wn = (wid >> 2) * 32;    // warp N offset

    float acc[2][4][4];
    #pragma unroll
    for (int i = 0; i < 2; i++)
        #pragma unroll
        for (int j = 0; j < 4; j++)
            #pragma unroll
            for (int r = 0; r < 4; r++) acc[i][j][r] = 0.f;

    uint32_t sbA[NSTAGE], sbB[NSTAGE];
    #pragma unroll
    for (int s = 0; s < NSTAGE; s++) {
        sbA[s] = smem_u32(&sA[s][0]);
        sbB[s] = smem_u32(&sB[s][0]);
    }

    // stage loader: A 512 chunks (2/thread), B 128 chunks (tid<128)
    auto load_stage = [&](int s, int kt) {
        #pragma unroll
        for (int i = 0; i < 2; i++) {
            int id = tid + i * 256;
            int row = id >> 2, c = id & 3;
            cp16(sbA[s] + (uint32_t)(row * ROWPAD + c * 4) * 4,
                 A + (size_t)(m0 + row) * GK + kt * 16 + c * 4);
        }
        if (tid < 128) {
            int row = tid >> 1, c = tid & 1;
            cp16(sbB[s] + (uint32_t)(row * BPITCH + c * 8) * 2,
                 Wt + (size_t)(n0 + row) * GK + kt * 16 + c * 8);
        }
    };

    load_stage(0, 0);
    asm volatile("cp.async.commit_group;" ::: "memory");
    load_stage(1, 1);
    asm volatile("cp.async.commit_group;" ::: "memory");

    #pragma unroll 1
    for (int kt = 0; kt < NKT; kt++) {
        if (kt < NKT - 1) {
            asm volatile("cp.async.wait_group 1;" ::: "memory");
        } else {
            asm volatile("cp.async.wait_group 0;" ::: "memory");
        }
        __syncthreads();

        if (kt + 2 < NKT) {
            load_stage((kt + 2) % NSTAGE, kt + 2);
            asm volatile("cp.async.commit_group;" ::: "memory");
        }

        const float*  As = sA[kt % NSTAGE];
        const __half* Bs = sB[kt % NSTAGE];

        uint32_t a[2][4], b[4][2];
        #pragma unroll
        for (int mf = 0; mf < 2; mf++) {
            int r = wm + mf * 16 + g;
            a[mf][0] = pack_h2(*(const float2*)&As[r * ROWPAD + tig * 2]);
            a[mf][1] = pack_h2(*(const float2*)&As[(r + 8) * ROWPAD + tig * 2]);
            a[mf][2] = pack_h2(*(const float2*)&As[r * ROWPAD + tig * 2 + 8]);
            a[mf][3] = pack_h2(*(const float2*)&As[(r + 8) * ROWPAD + tig * 2 + 8]);
        }
        #pragma unroll
        for (int nf = 0; nf < 4; nf++) {
            int rb = wn + nf * 8 + g;
            b[nf][0] = *(const uint32_t*)&Bs[rb * BPITCH + tig * 2];
            b[nf][1] = *(const uint32_t*)&Bs[rb * BPITCH + tig * 2 + 8];
        }
        #pragma unroll
        for (int mf = 0; mf < 2; mf++)
            #pragma unroll
            for (int nf = 0; nf < 4; nf++) {
                asm volatile(
                    "mma.sync.aligned.m16n8k16.row.col.f32.f16.f16.f32 "
                    "{%0,%1,%2,%3}, {%4,%5,%6,%7}, {%8,%9}, {%0,%1,%2,%3};"
                    : "+f"(acc[mf][nf][0]), "+f"(acc[mf][nf][1]),
                      "+f"(acc[mf][nf][2]), "+f"(acc[mf][nf][3])
                    : "r"(a[mf][0]), "r"(a[mf][1]), "r"(a[mf][2]), "r"(a[mf][3]),
                      "r"(b[nf][0]), "r"(b[nf][1]));
            }
    }

    // epilogue: add bias, write float2 pairs
    #pragma unroll
    for (int nf = 0; nf < 4; nf++) {
        const int col = n0 + wn + nf * 8 + tig * 2;
        const float2 bb = *(const float2*)(bias + col);
        #pragma unroll
        for (int mf = 0; mf < 2; mf++) {
            const int row = m0 + wm + mf * 16 + g;
            float2 v0 = make_float2(acc[mf][nf][0] + bb.x, acc[mf][nf][1] + bb.y);
            float2 v1 = make_float2(acc[mf][nf][2] + bb.x, acc[mf][nf][3] + bb.y);
            *(float2*)(C + (size_t)row * N + col) = v0;
            *(float2*)(C + (size_t)(row + 8) * N + col) = v1;
        }
    }
}

// W [K=256, N] fp32 row-major  ->  Wt [N, K] fp16 row-major
__global__ void pack_wt(const float* __restrict__ W, __half* __restrict__ Wt, int N) {
    __shared__ float t[32][33];
    int bx = blockIdx.x * 32;   // n tile
    int by = blockIdx.y * 32;   // k tile
    int x = threadIdx.x, y = threadIdx.y;
    #pragma unroll
    for (int i = 0; i < 32; i += 8)
        t[y + i][x] = W[(size_t)(by + y + i) * N + bx + x];
    __syncthreads();
    #pragma unroll
    for (int i = 0; i < 32; i += 8)
        Wt[(size_t)(bx + y + i) * GK + by + x] = __float2half_rn(t[x][y + i]);
}

// ---------------- prep: softmax + bilinear weights + clamped corner indices ----------------
// One thread per (b,n,h). Emits, per sample: float4 weights (x attn) and int4
// pyramid indices (pre-scaled by HIDDEN, clamped; invalid corners get weight 0).
__global__ void msda_prep(const float* __restrict__ qp,
                          const float* __restrict__ refpts,
                          float4* __restrict__ sw,
                          int4* __restrict__ si)
{
    int t = blockIdx.x * blockDim.x + threadIdx.x;
    if (t >= BNH) return;
    int bn = t / HNUM;

    const float* q = qp + (size_t)t * 48;

    float lg[16];
    float mx = -1e30f;
    #pragma unroll
    for (int s = 0; s < 16; s++) { lg[s] = q[s * 3 + 2]; mx = fmaxf(mx, lg[s]); }
    float sum = 0.f;
    #pragma unroll
    for (int s = 0; s < 16; s++) { lg[s] = expf(lg[s] - mx); sum += lg[s]; }
    float inv = 1.0f / sum;

    float rx = refpts[bn * 2 + 0];
    float ry = refpts[bn * 2 + 1];

    #pragma unroll
    for (int s = 0; s < 16; s++) {
        int l = s >> 2;
        int sh = c_sh[l];
        float fs = (float)sh;
        int st = c_start[l];
        float aw = lg[s] * inv;

        float px = rx + q[s * 3 + 0] / fs;
        float py = ry + q[s * 3 + 1] / fs;
        float x = px * fs - 0.5f;
        float y = py * fs - 0.5f;
        float x0f = floorf(x), y0f = floorf(y);
        int x0 = (int)x0f, y0 = (int)y0f;
        float wx = x - x0f, wy = y - y0f;

        float w00 = (1.f - wx) * (1.f - wy) * aw;
        float w10 = wx * (1.f - wy) * aw;
        float w01 = (1.f - wx) * wy * aw;
        float w11 = wx * wy * aw;

        bool vx0 = (x0 >= 0) & (x0 < sh);
        bool vx1 = (x0 + 1 >= 0) & (x0 + 1 < sh);
        bool vy0 = (y0 >= 0) & (y0 < sh);
        bool vy1 = (y0 + 1 >= 0) & (y0 + 1 < sh);

        int xc0 = min(max(x0, 0), sh - 1);
        int xc1 = min(max(x0 + 1, 0), sh - 1);
        int yc0 = min(max(y0, 0), sh - 1);
        int yc1 = min(max(y0 + 1, 0), sh - 1);

        float4 w4;
        w4.x = (vx0 & vy0) ? w00 : 0.f;
        w4.y = (vx1 & vy0) ? w10 : 0.f;
        w4.z = (vx0 & vy1) ? w01 : 0.f;
        w4.w = (vx1 & vy1) ? w11 : 0.f;

        int4 i4;
        i4.x = (st + yc0 * sh + xc0) * HIDDEN;
        i4.y = (st + yc0 * sh + xc1) * HIDDEN;
        i4.z = (st + yc1 * sh + xc0) * HIDDEN;
        i4.w = (st + yc1 * sh + xc1) * HIDDEN;

        sw[(size_t)t * 16 + s] = w4;
        si[(size_t)t * 16 + s] = i4;
    }
}

// ---------------- lean gather: one warp per (b,n,h), lane = channel ----------------
__global__ __launch_bounds__(256) void msda_sample(
    const float* __restrict__ img_p,
    const float4* __restrict__ sw,
    const int4* __restrict__ si,
    float* __restrict__ out)
{
    int w = blockIdx.x * 8 + (threadIdx.x >> 5);
    int lane = threadIdx.x & 31;

    int h = w % HNUM;
    int b = w / (NQ * HNUM);

    const float* base = img_p + (size_t)b * ITOT * HIDDEN + h * CHD + lane;
    const float4* wp = sw + (size_t)w * 16;
    const int4*   ip = si + (size_t)w * 16;

    float acc = 0.f;
    #pragma unroll
    for (int s = 0; s < 16; s++) {
        float4 wt = __ldg(wp + s);   // warp-uniform -> broadcast
        int4   ix = __ldg(ip + s);
        acc += wt.x * __ldg(base + ix.x);
        acc += wt.y * __ldg(base + ix.y);
        acc += wt.z * __ldg(base + ix.z);
        acc += wt.w * __ldg(base + ix.w);
    }
    out[(size_t)w * CHD + lane] = acc;
}

// ---------------- launch ----------------
extern "C" void kernel_launch(void* const* d_in, const int* in_sizes, int n_in,
                              void* d_out, int out_size)
{
    const float* img     = (const float*)d_in[0];
    const float* queries = (const float*)d_in[2];
    const float* refpts  = (const float*)d_in[3];
    const float* W_img   = (const float*)d_in[4];
    const float* b_img   = (const float*)d_in[5];
    const float* W_q     = (const float*)d_in[6];
    const float* b_q     = (const float*)d_in[7];
    const float* W_out   = (const float*)d_in[8];
    const float* b_out   = (const float*)d_in[9];
    float* out = (float*)d_out;

    float *img_p, *qp, *hidden;
    __half *Wt1, *Wt2, *Wt3;
    float4* sw;
    int4* si;
    cudaGetSymbolAddress((void**)&img_p,  g_img_p);
    cudaGetSymbolAddress((void**)&qp,     g_qp);
    cudaGetSymbolAddress((void**)&sw,     g_sw);
    cudaGetSymbolAddress((void**)&si,     g_si);
    cudaGetSymbolAddress((void**)&hidden, g_hidden);
    cudaGetSymbolAddress((void**)&Wt1,    g_Wt1);
    cudaGetSymbolAddress((void**)&Wt2,    g_Wt2);
    cudaGetSymbolAddress((void**)&Wt3,    g_Wt3);

    // 0) pack weights: transpose to [N,K] + fp16 rounding
    {
        dim3 blk(32, 8);
        pack_wt<<<dim3(HIDDEN / 32, GK / 32), blk>>>(W_img, Wt1, HIDDEN);
        pack_wt<<<dim3(QPW    / 32, GK / 32), blk>>>(W_q,   Wt2, QPW);
        pack_wt<<<dim3(EMBD   / 32, GK / 32), blk>>>(W_out, Wt3, EMBD);
    }
    // 1) img projection: [174080,256] @ [256,256] + b
    hgemm<<<dim3(HIDDEN / 64, (BATCH * ITOT) / 128), 256>>>(
        img, Wt1, b_img, img_p, BATCH * ITOT, HIDDEN);
    // 2) query projection: [8192,256] @ [256,384] + b
    hgemm<<<dim3(QPW / 64, (BATCH * NQ) / 128), 256>>>(
        queries, Wt2, b_q, qp, BATCH * NQ, QPW);
    // 3) softmax + weights/indices precompute
    msda_prep<<<(BNH + 127) / 128, 128>>>(qp, refpts, sw, si);
    // 4) gather + attention reduce
    msda_sample<<<BNH / 8, 256>>>(img_p, sw, si, hidden);
    // 5) output projection: [8192,256] @ [256,256] + b
    hgemm<<<dim3(HIDDEN / 64, (BATCH * NQ) / 128), 256>>>(
        hidden, Wt3, b_out, out, BATCH * NQ, HIDDEN);
}